// round 4
// baseline (speedup 1.0000x reference)
#include <cuda_runtime.h>

// Fixed problem shapes
static constexpr int NP     = 128;           // partitions
static constexpr int Cc     = 32;            // key channels
static constexpr int Dd     = 128;           // value/query dim
static constexpr int Bb     = 4;
static constexpr int Ss     = 2048;
static constexpr int Kk     = 2;
static constexpr int NPAIRS = Bb * Ss * Kk;  // 16384
static constexpr int NTOK   = Bb * Ss;       // 8192

static constexpr int CAP     = 2048;         // per-partition match capacity
static constexpr int NTHREAD = 512;
static constexpr int OUT_N4  = NTOK * Dd / 4;      // 262144 float4 outputs

// Persistent device state.
__device__ float g_M[NP * Dd];               // per-partition mean-state row
// Grid barrier: monotonic phase counter survives graph replays correctly
// (count is reset to 0 by the releasing block each time).
__device__ unsigned          g_bar_count = 0;
__device__ volatile unsigned g_bar_phase = 0;

// ---------------------------------------------------------------------------
// Single persistent kernel, 128 blocks (one per partition, single wave on
// 148 SMs -> spin barrier is deadlock-free), 512 threads.
//
//   Phase 1: scan all 16K indices (int4), compact matching pair indices j
//            deterministically via two-level shfl scan (ascending-j order).
//   Phase 1.5: cooperatively compute w[m] = mean_c keys[j_m, c]
//            (8 threads per 128B key row; each key row read once chip-wide).
//   Phase 2: M[p,d] = sum_m w[m] * values[j_m/2, d]; 4 slices + smem reduce.
//   -- grid barrier (threadfence + atomic arrive + volatile phase spin) --
//   Phase 3: out[t,d] = (M[i0,d]+M[i1,d]) * q[t,d], grid-strided float4.
// ---------------------------------------------------------------------------
__global__ void __launch_bounds__(NTHREAD, 1) k_fused(
    const int*   __restrict__ idx,
    const float* __restrict__ keys,
    const float* __restrict__ values,
    const float* __restrict__ q,
    float*       __restrict__ out)
{
    __shared__ int      js[CAP];
    __shared__ float    wls[CAP];
    __shared__ int      wsum[16];
    __shared__ float    red[NTHREAD];
    __shared__ unsigned entry_phase;

    const int p    = blockIdx.x;
    const int tid  = threadIdx.x;
    const int lane = tid & 31;
    const int wid  = tid >> 5;

    // Snapshot barrier phase before anyone can possibly release it.
    if (tid == 0) entry_phase = g_bar_phase;

    // ---- Phase 1a: load my 32 indices (8 x int4, coalesced), count matches
    int4 my[8];
    const int4* idx4 = (const int4*)idx + tid * 8;
    int cnt = 0;
    #pragma unroll
    for (int i = 0; i < 8; i++) {
        my[i] = idx4[i];
        cnt += (my[i].x == p) + (my[i].y == p) + (my[i].z == p) + (my[i].w == p);
    }

    // ---- Phase 1b: two-level exclusive scan (warp shfl + 16-entry top)
    int inc = cnt;
    #pragma unroll
    for (int o = 1; o < 32; o <<= 1) {
        int v = __shfl_up_sync(0xFFFFFFFFu, inc, o);
        if (lane >= o) inc += v;
    }
    if (lane == 31) wsum[wid] = inc;
    __syncthreads();
    if (wid == 0) {
        int v = (lane < 16) ? wsum[lane] : 0;
        #pragma unroll
        for (int o = 1; o < 16; o <<= 1) {
            int u = __shfl_up_sync(0xFFFFFFFFu, v, o);
            if (lane >= o) v += u;
        }
        if (lane < 16) wsum[lane] = v;        // inclusive prefix of warp totals
    }
    __syncthreads();
    int n   = wsum[15];
    int pos = (wid ? wsum[wid - 1] : 0) + (inc - cnt);

    // ---- Phase 1c: emit matched pair indices (ascending-j, deterministic)
    #pragma unroll
    for (int i = 0; i < 8; i++) {
        const int j = tid * 32 + i * 4;
        if (my[i].x == p && pos < CAP) js[pos++] = j + 0;
        if (my[i].y == p && pos < CAP) js[pos++] = j + 1;
        if (my[i].z == p && pos < CAP) js[pos++] = j + 2;
        if (my[i].w == p && pos < CAP) js[pos++] = j + 3;
    }
    if (n > CAP) n = CAP;
    __syncthreads();

    // ---- Phase 1.5: cooperative weights. 8 threads per key row (float4 +
    // octet shfl-reduce); 64 rows per sweep.
    const int lane8 = tid & 7;
    const int row8  = tid >> 3;
    for (int base = 0; base < n; base += NTHREAD / 8) {
        const int m = base + row8;
        float s = 0.f;
        if (m < n) {
            float4 v = ((const float4*)keys)[(size_t)js[m] * (Cc / 4) + lane8];
            s = (v.x + v.y) + (v.z + v.w);
        }
        s += __shfl_xor_sync(0xFFFFFFFFu, s, 1);
        s += __shfl_xor_sync(0xFFFFFFFFu, s, 2);
        s += __shfl_xor_sync(0xFFFFFFFFu, s, 4);
        if (m < n && lane8 == 0) wls[m] = s * (1.0f / Cc);
    }
    __syncthreads();

    // ---- Phase 2: sliced gather-accumulate, 4-way smem reduce, write M row
    {
        const int d     = tid & (Dd - 1);
        const int slice = tid >> 7;
        float acc = 0.f;
        for (int m = slice; m < n; m += 4)
            acc += wls[m] * values[(size_t)(js[m] >> 1) * Dd + d];
        red[tid] = acc;
        __syncthreads();
        if (tid < Dd)
            g_M[p * Dd + tid] = (red[tid] + red[tid + 128])
                              + (red[tid + 256] + red[tid + 384]);
    }

    // ---- Grid barrier: all 128 blocks' M rows visible before phase 3
    __syncthreads();
    if (tid == 0) {
        __threadfence();                       // publish g_M writes
        const unsigned tgt = entry_phase + 1;
        if (atomicAdd(&g_bar_count, 1u) == NP - 1) {
            g_bar_count = 0;
            __threadfence();
            g_bar_phase = tgt;                 // release
        } else {
            while (g_bar_phase < tgt) { }
        }
    }
    __syncthreads();

    // ---- Phase 3: out[t,:] = (M[i0,:]+M[i1,:]) * q[t,:], float4 stream
    const float4* M4 = (const float4*)g_M;
    for (int i = blockIdx.x * NTHREAD + tid; i < OUT_N4; i += NP * NTHREAD) {
        const int tok = i >> 5;                // 32 float4 per token row
        const int d4  = i & 31;
        const int2 ii = ((const int2*)idx)[tok];
        float4 m0 = M4[ii.x * 32 + d4];
        float4 m1 = M4[ii.y * 32 + d4];
        float4 qv = ((const float4*)q)[i];
        float4 o;
        o.x = (m0.x + m1.x) * qv.x;
        o.y = (m0.y + m1.y) * qv.y;
        o.z = (m0.z + m1.z) * qv.z;
        o.w = (m0.w + m1.w) * qv.w;
        ((float4*)out)[i] = o;
    }
}

extern "C" void kernel_launch(void* const* d_in, const int* in_sizes, int n_in,
                              void* d_out, int out_size)
{
    const int*   idx     = (const int*)  d_in[0];  // [B,S,K] int32
    const float* keys    = (const float*)d_in[1];  // [B,S,K,C] f32
    const float* values  = (const float*)d_in[2];  // [B,S,D]   f32
    const float* queries = (const float*)d_in[3];  // [B,S,D]   f32
    float*       out     = (float*)d_out;          // [B,S,D]   f32

    (void)in_sizes; (void)n_in; (void)out_size;

    k_fused<<<NP, NTHREAD>>>(idx, keys, values, queries, out);
}

// round 5
// speedup vs baseline: 1.0151x; 1.0151x over previous
#include <cuda_runtime.h>

// Fixed problem shapes
static constexpr int NP     = 128;           // partitions
static constexpr int Cc     = 32;            // key channels
static constexpr int Dd     = 128;           // value/query dim
static constexpr int Bb     = 4;
static constexpr int Ss     = 2048;
static constexpr int Kk     = 2;
static constexpr int NPAIRS = Bb * Ss * Kk;  // 16384
static constexpr int NTOK   = Bb * Ss;       // 8192

static constexpr int HALFN   = NPAIRS / 2;   // 8192 pairs per half
static constexpr int CAP     = 1024;         // per-(p,half) match capacity
                                             // (mean 64, sigma 8 -> >100 sigma safe)
static constexpr int NTHR    = 256;
static constexpr int NBLK    = 2 * NP;       // 256 blocks = (partition, half)
static constexpr int OUT_N4  = NTOK * Dd / 4;        // 262144 float4 outputs
static constexpr int STRIDE4 = NBLK * NTHR;          // 65536 -> exactly 4 iters

// Persistent device state (fully rewritten every launch; no zero-init).
__device__ float g_P[2 * NP * Dd];           // per-(half,partition) partial rows
__device__ unsigned          g_bar_count = 0;
__device__ volatile unsigned g_bar_phase = 0; // monotonic across graph replays

// ---------------------------------------------------------------------------
// One kernel, 256 blocks x 256 threads (2 CTAs/SM, all co-resident -> spin
// grid barrier is deadlock-free).
// Block (p,h): scan half h of the 16K pair indices for idx==p, compact
// deterministically, compute w = mean_c keys[j,:] (1 row/thread, 8 loads in
// flight), accumulate partial row P[h][p][:] (4x-unrolled gather).
// -- grid barrier --
// Phase 3: out[t,d] = (P0[i0,d]+P1[i0,d]+P0[i1,d]+P1[i1,d]) * q[t,d],
// exact-4 unrolled float4 stream (all loads of all 4 iters independent).
// ---------------------------------------------------------------------------
__global__ void __launch_bounds__(NTHR, 2) k_fused(
    const int*   __restrict__ idx,
    const float* __restrict__ keys,
    const float* __restrict__ values,
    const float* __restrict__ q,
    float*       __restrict__ out)
{
    __shared__ int      js[CAP];
    __shared__ float    wls[CAP];
    __shared__ int      wsum[8];
    __shared__ float    red[NTHR];
    __shared__ unsigned entry_phase;

    const int p    = blockIdx.x >> 1;
    const int h    = blockIdx.x & 1;
    const int tid  = threadIdx.x;
    const int lane = tid & 31;
    const int wid  = tid >> 5;

    if (tid == 0) entry_phase = g_bar_phase;   // snapshot before any release

    // ---- Phase 1a: load my 32 indices from half h (8 x int4), count matches
    int4 my[8];
    const int4* idx4 = (const int4*)idx + h * (HALFN / 4) + tid * 8;
    int cnt = 0;
    #pragma unroll
    for (int i = 0; i < 8; i++) {
        my[i] = idx4[i];
        cnt += (my[i].x == p) + (my[i].y == p) + (my[i].z == p) + (my[i].w == p);
    }

    // ---- Phase 1b: two-level exclusive scan (warp shfl + 8-entry top)
    int inc = cnt;
    #pragma unroll
    for (int o = 1; o < 32; o <<= 1) {
        int v = __shfl_up_sync(0xFFFFFFFFu, inc, o);
        if (lane >= o) inc += v;
    }
    if (lane == 31) wsum[wid] = inc;
    __syncthreads();
    if (wid == 0) {
        int v = (lane < 8) ? wsum[lane] : 0;
        #pragma unroll
        for (int o = 1; o < 8; o <<= 1) {
            int u = __shfl_up_sync(0xFFFFFFFFu, v, o);
            if (lane >= o) v += u;
        }
        if (lane < 8) wsum[lane] = v;          // inclusive prefix of warp totals
    }
    __syncthreads();
    int n   = wsum[7];
    int pos = (wid ? wsum[wid - 1] : 0) + (inc - cnt);

    // ---- Phase 1c: emit matched pair indices (ascending-j, deterministic)
    #pragma unroll
    for (int i = 0; i < 8; i++) {
        const int j = h * HALFN + tid * 32 + i * 4;
        if (my[i].x == p && pos < CAP) js[pos++] = j + 0;
        if (my[i].y == p && pos < CAP) js[pos++] = j + 1;
        if (my[i].z == p && pos < CAP) js[pos++] = j + 2;
        if (my[i].w == p && pos < CAP) js[pos++] = j + 3;
    }
    if (n > CAP) n = CAP;
    __syncthreads();

    // ---- Phase 1.5: weights, one key row per thread -> 8 independent
    // float4 loads in flight per thread, full sum in-register, no shuffles.
    for (int m = tid; m < n; m += NTHR) {
        const float4* kp = (const float4*)keys + (size_t)js[m] * (Cc / 4);
        float4 a = kp[0], b = kp[1], c = kp[2], dd4 = kp[3];
        float4 e = kp[4], f = kp[5], g2 = kp[6], h4 = kp[7];
        float s = ((a.x + a.y) + (a.z + a.w)) + ((b.x + b.y) + (b.z + b.w))
                + ((c.x + c.y) + (c.z + c.w)) + ((dd4.x + dd4.y) + (dd4.z + dd4.w))
                + ((e.x + e.y) + (e.z + e.w)) + ((f.x + f.y) + (f.z + f.w))
                + ((g2.x + g2.y) + (g2.z + g2.w)) + ((h4.x + h4.y) + (h4.z + h4.w));
        wls[m] = s * (1.0f / Cc);
    }
    __syncthreads();

    // ---- Phase 2: sliced gather-accumulate, 4x unrolled (4 independent
    // value-row loads per iteration), then 2-way smem reduce.
    {
        const int d     = tid & (Dd - 1);
        const int slice = tid >> 7;              // 2 slices of 128 d-threads
        float acc = 0.f;
        int m = slice;
        for (; m + 6 < n; m += 8) {
            const int   j0 = js[m],     j1 = js[m + 2];
            const int   j2 = js[m + 4], j3 = js[m + 6];
            const float w0 = wls[m],     w1 = wls[m + 2];
            const float w2 = wls[m + 4], w3 = wls[m + 6];
            const float v0 = values[(size_t)(j0 >> 1) * Dd + d];
            const float v1 = values[(size_t)(j1 >> 1) * Dd + d];
            const float v2 = values[(size_t)(j2 >> 1) * Dd + d];
            const float v3 = values[(size_t)(j3 >> 1) * Dd + d];
            acc += w0 * v0 + w1 * v1 + w2 * v2 + w3 * v3;
        }
        for (; m < n; m += 2)
            acc += wls[m] * values[(size_t)(js[m] >> 1) * Dd + d];
        red[tid] = acc;
        __syncthreads();
        if (tid < Dd)
            g_P[(h * NP + p) * Dd + tid] = red[tid] + red[tid + 128];
    }

    // ---- Grid barrier (256 arrivals; all CTAs co-resident)
    __syncthreads();
    if (tid == 0) {
        __threadfence();                         // publish g_P writes
        const unsigned tgt = entry_phase + 1;
        if (atomicAdd(&g_bar_count, 1u) == NBLK - 1) {
            g_bar_count = 0;
            __threadfence();
            g_bar_phase = tgt;                   // release
        } else {
            while (g_bar_phase < tgt) __nanosleep(64);
        }
    }
    __syncthreads();

    // ---- Phase 3: exact-4 unrolled output stream. All 4 iterations'
    // loads are independent -> deep MLP per thread.
    const float4* P0 = (const float4*)g_P;           // half 0 rows
    const float4* P1 = P0 + NP * Dd / 4;             // half 1 rows
    const int base = blockIdx.x * NTHR + tid;        // 0 .. 65535
    #pragma unroll
    for (int k = 0; k < 4; k++) {
        const int i   = base + k * STRIDE4;
        const int tok = i >> 5;                      // 32 float4 per token row
        const int d4  = i & 31;
        const int2 ii = ((const int2*)idx)[tok];
        float4 a0 = P0[ii.x * 32 + d4];
        float4 b0 = P1[ii.x * 32 + d4];
        float4 a1 = P0[ii.y * 32 + d4];
        float4 b1 = P1[ii.y * 32 + d4];
        float4 qv = ((const float4*)q)[i];
        float4 o;
        o.x = ((a0.x + b0.x) + (a1.x + b1.x)) * qv.x;
        o.y = ((a0.y + b0.y) + (a1.y + b1.y)) * qv.y;
        o.z = ((a0.z + b0.z) + (a1.z + b1.z)) * qv.z;
        o.w = ((a0.w + b0.w) + (a1.w + b1.w)) * qv.w;
        ((float4*)out)[i] = o;
    }
}

extern "C" void kernel_launch(void* const* d_in, const int* in_sizes, int n_in,
                              void* d_out, int out_size)
{
    const int*   idx     = (const int*)  d_in[0];  // [B,S,K] int32
    const float* keys    = (const float*)d_in[1];  // [B,S,K,C] f32
    const float* values  = (const float*)d_in[2];  // [B,S,D]   f32
    const float* queries = (const float*)d_in[3];  // [B,S,D]   f32
    float*       out     = (float*)d_out;          // [B,S,D]   f32

    (void)in_sizes; (void)n_in; (void)out_size;

    k_fused<<<NBLK, NTHR>>>(idx, keys, values, queries, out);
}

// round 6
// speedup vs baseline: 1.1750x; 1.1575x over previous
#include <cuda_runtime.h>

// Fixed problem shapes
static constexpr int NP     = 128;           // partitions
static constexpr int Cc     = 32;            // key channels
static constexpr int Dd     = 128;           // value/query dim
static constexpr int Bb     = 4;
static constexpr int Ss     = 2048;
static constexpr int Kk     = 2;
static constexpr int NPAIRS = Bb * Ss * Kk;  // 16384
static constexpr int NTOK   = Bb * Ss;       // 8192

static constexpr int NTHR   = 1024;
static constexpr int NBLK   = NP;            // 128 blocks, one per partition
static constexpr int CAP    = 1024;          // match capacity (mean 128, sigma 11)
static constexpr int PER    = NPAIRS / 4 / NTHR;   // 4 int4 per thread
static constexpr int OUT_N4 = NTOK * Dd / 4;       // 262144 float4 outputs
static constexpr int STR    = NBLK * NTHR;         // 131072 -> exactly 2 iters

// Persistent device state (fully rewritten every launch).
__device__ float g_M[NP * Dd];
__device__ unsigned          g_bar_count = 0;
__device__ volatile unsigned g_bar_phase = 0;  // monotonic across graph replays

// ---------------------------------------------------------------------------
// 128 blocks x 1024 threads, one per partition, single co-resident wave.
//   Phase 1: coalesced strided int4 scan of all 16K indices; two-level shfl
//            scan -> deterministic compaction (fixed permutation order).
//   Phase 1.5: w[m] = mean_c keys[j_m,:], one row per thread (single wave).
//   Phase 2: float4 gather, thread=(slice,d4), 32 slices -> ~4 matches per
//            thread (short chain), 5-step smem float4 tree reduce -> g_M row.
//   (prefetch phase-3 q/idx, then grid barrier hides their DRAM latency)
//   Phase 3: out = (M[i0]+M[i1]) * q, 2 exact iterations, float4.
// ---------------------------------------------------------------------------
__global__ void __launch_bounds__(NTHR, 1) k_fused(
    const int*   __restrict__ idx,
    const float* __restrict__ keys,
    const float* __restrict__ values,
    const float* __restrict__ q,
    float*       __restrict__ out)
{
    __shared__ int      js[CAP];
    __shared__ float    wls[CAP];
    __shared__ int      wsum[32];
    __shared__ float4   red4[NTHR];
    __shared__ unsigned entry_phase;

    const int p    = blockIdx.x;
    const int tid  = threadIdx.x;
    const int lane = tid & 31;
    const int wid  = tid >> 5;

    if (tid == 0) entry_phase = g_bar_phase;   // snapshot before any release

    // ---- Phase 1a: coalesced strided idx load (4 int4/thread), count
    const int4* idx4 = (const int4*)idx;
    int4 my[PER];
    int cnt = 0;
    #pragma unroll
    for (int i = 0; i < PER; i++) {
        my[i] = idx4[i * NTHR + tid];
        cnt += (my[i].x == p) + (my[i].y == p) + (my[i].z == p) + (my[i].w == p);
    }

    // ---- Phase 1b: two-level exclusive scan (warp shfl + 32-entry top)
    int inc = cnt;
    #pragma unroll
    for (int o = 1; o < 32; o <<= 1) {
        int v = __shfl_up_sync(0xFFFFFFFFu, inc, o);
        if (lane >= o) inc += v;
    }
    if (lane == 31) wsum[wid] = inc;
    __syncthreads();
    if (wid == 0) {
        int v = wsum[lane];
        #pragma unroll
        for (int o = 1; o < 32; o <<= 1) {
            int u = __shfl_up_sync(0xFFFFFFFFu, v, o);
            if (lane >= o) v += u;
        }
        wsum[lane] = v;                        // inclusive prefix of warp totals
    }
    __syncthreads();
    int n   = wsum[31];
    int pos = (wid ? wsum[wid - 1] : 0) + (inc - cnt);

    // ---- Phase 1c: emit matched pair indices (fixed deterministic order)
    #pragma unroll
    for (int i = 0; i < PER; i++) {
        const int j = (i * NTHR + tid) * 4;
        if (my[i].x == p && pos < CAP) js[pos++] = j + 0;
        if (my[i].y == p && pos < CAP) js[pos++] = j + 1;
        if (my[i].z == p && pos < CAP) js[pos++] = j + 2;
        if (my[i].w == p && pos < CAP) js[pos++] = j + 3;
    }
    if (n > CAP) n = CAP;
    __syncthreads();

    // ---- Phase 1.5: weights, one 128B key row per thread (single wave,
    // 8 independent float4 loads in flight per active thread).
    for (int m = tid; m < n; m += NTHR) {
        const float4* kp = (const float4*)keys + (size_t)js[m] * (Cc / 4);
        float4 a = kp[0], b = kp[1], c = kp[2], d0 = kp[3];
        float4 e = kp[4], f = kp[5], g2 = kp[6], h4 = kp[7];
        float s = ((a.x + a.y) + (a.z + a.w)) + ((b.x + b.y) + (b.z + b.w))
                + ((c.x + c.y) + (c.z + c.w)) + ((d0.x + d0.y) + (d0.z + d0.w))
                + ((e.x + e.y) + (e.z + e.w)) + ((f.x + f.y) + (f.z + f.w))
                + ((g2.x + g2.y) + (g2.z + g2.w)) + ((h4.x + h4.y) + (h4.z + h4.w));
        wls[m] = s * (1.0f / Cc);
    }
    __syncthreads();

    // ---- Phase 2: float4 gather. thread = (slice, d4): 32 slices x 32 d4.
    // Each thread: ~n/32 ~= 4 independent row-quarters. Coalesced 512B rows.
    {
        const int slice = tid >> 5;
        const int d4    = tid & 31;
        const float4* V4 = (const float4*)values;
        float4 acc = make_float4(0.f, 0.f, 0.f, 0.f);
        int m = slice;
        for (; m + 32 < n; m += 64) {                 // 2 independent loads/iter
            const int   t0 = js[m] >> 1,   t1 = js[m + 32] >> 1;
            const float w0 = wls[m],       w1 = wls[m + 32];
            float4 v0 = V4[t0 * 32 + d4];
            float4 v1 = V4[t1 * 32 + d4];
            acc.x += w0 * v0.x + w1 * v1.x;
            acc.y += w0 * v0.y + w1 * v1.y;
            acc.z += w0 * v0.z + w1 * v1.z;
            acc.w += w0 * v0.w + w1 * v1.w;
        }
        if (m < n) {
            const float w0 = wls[m];
            float4 v0 = V4[(js[m] >> 1) * 32 + d4];
            acc.x += w0 * v0.x; acc.y += w0 * v0.y;
            acc.z += w0 * v0.z; acc.w += w0 * v0.w;
        }
        red4[tid] = acc;                              // slice-major layout
        __syncthreads();
        #pragma unroll
        for (int off = NTHR / 2; off >= 32; off >>= 1) {
            if (tid < off) {
                float4 o4 = red4[tid + off];
                float4 s4 = red4[tid];
                s4.x += o4.x; s4.y += o4.y; s4.z += o4.z; s4.w += o4.w;
                red4[tid] = s4;
            }
            __syncthreads();
        }
        if (tid < 32)                                 // 512B coalesced M row
            ((float4*)g_M)[p * 32 + tid] = red4[tid];
    }

    // ---- Prefetch phase-3 inputs (independent of g_M) BEFORE the barrier:
    // their DRAM latency is absorbed by the barrier wait.
    const int  base = blockIdx.x * NTHR + tid;        // 0 .. 131071
    const int2 ii0  = ((const int2*)idx)[base >> 5];
    const int2 ii1  = ((const int2*)idx)[(base + STR) >> 5];
    const float4 qv0 = ((const float4*)q)[base];
    const float4 qv1 = ((const float4*)q)[base + STR];

    // ---- Grid barrier (128 arrivals; all CTAs co-resident)
    __syncthreads();
    if (tid == 0) {
        __threadfence();                              // publish g_M
        const unsigned tgt = entry_phase + 1;
        if (atomicAdd(&g_bar_count, 1u) == NBLK - 1) {
            g_bar_count = 0;
            __threadfence();
            g_bar_phase = tgt;                        // release
        } else {
            while (g_bar_phase < tgt) __nanosleep(32);
        }
    }
    __syncthreads();

    // ---- Phase 3: two exact iterations, L2-resident M gathers + store
    const float4* M4 = (const float4*)g_M;
    {
        const int d4 = base & 31;
        float4 a = M4[ii0.x * 32 + d4];
        float4 b = M4[ii0.y * 32 + d4];
        float4 o;
        o.x = (a.x + b.x) * qv0.x;
        o.y = (a.y + b.y) * qv0.y;
        o.z = (a.z + b.z) * qv0.z;
        o.w = (a.w + b.w) * qv0.w;
        ((float4*)out)[base] = o;
    }
    {
        const int i2 = base + STR;
        const int d4 = i2 & 31;
        float4 a = M4[ii1.x * 32 + d4];
        float4 b = M4[ii1.y * 32 + d4];
        float4 o;
        o.x = (a.x + b.x) * qv1.x;
        o.y = (a.y + b.y) * qv1.y;
        o.z = (a.z + b.z) * qv1.z;
        o.w = (a.w + b.w) * qv1.w;
        ((float4*)out)[i2] = o;
    }
}

extern "C" void kernel_launch(void* const* d_in, const int* in_sizes, int n_in,
                              void* d_out, int out_size)
{
    const int*   idx     = (const int*)  d_in[0];  // [B,S,K] int32
    const float* keys    = (const float*)d_in[1];  // [B,S,K,C] f32
    const float* values  = (const float*)d_in[2];  // [B,S,D]   f32
    const float* queries = (const float*)d_in[3];  // [B,S,D]   f32
    float*       out     = (float*)d_out;          // [B,S,D]   f32

    (void)in_sizes; (void)n_in; (void)out_size;

    k_fused<<<NBLK, NTHR>>>(idx, keys, values, queries, out);
}

// round 7
// speedup vs baseline: 1.1809x; 1.0050x over previous
#include <cuda_runtime.h>

// Fixed problem shapes
static constexpr int NP     = 128;           // partitions
static constexpr int Cc     = 32;            // key channels
static constexpr int Dd     = 128;           // value/query dim
static constexpr int Bb     = 4;
static constexpr int Ss     = 2048;
static constexpr int Kk     = 2;
static constexpr int NPAIRS = Bb * Ss * Kk;  // 16384
static constexpr int NTOK   = Bb * Ss;       // 8192

static constexpr int NTHR   = 1024;
static constexpr int NBLK   = 2 * NP;        // 256 blocks = (partition, half)
static constexpr int HALFN  = NPAIRS / 2;    // 8192 pairs per half
static constexpr int PER    = HALFN / 4 / NTHR;    // 2 int4 per thread
static constexpr int CAP    = 512;           // per-(p,half) capacity (mean 64, sigma 8)
static constexpr int OUT_N4 = NTOK * Dd / 4; // 262144 == NBLK*NTHR -> 1 f4/thread

// Persistent device state (fully rewritten every launch).
__device__ float g_P[2 * NP * Dd];           // per-(half,partition) partial rows
__device__ unsigned          g_bar_count = 0;
__device__ volatile unsigned g_bar_phase = 0;  // monotonic across graph replays

// ---------------------------------------------------------------------------
// 256 blocks x 1024 threads, 2 CTAs/SM (launch_bounds caps regs at 32 so
// 2048 threads/SM are resident -> n_conc=296 >= 256, spin barrier safe).
// Block (p,h):
//   Phase 1: scan half h of idx (2 int4/thread, strided-coalesced), two-level
//            shfl scan -> deterministic compaction of ~64 matches.
//   Phase 1.5: w[m] = mean_c keys[j_m,:], 8 threads/row octet-shfl (1 sweep).
//   Phase 2: float4 gather thread=(slice,d4), ~2 matches/thread; transpose
//            smem + warp-shfl reduce (single barrier) -> g_P[h][p] row.
//   (prefetch q/idx for phase 3, grid barrier absorbs their DRAM latency)
//   Phase 3: out = (P0[i0]+P1[i0]+P0[i1]+P1[i1]) * q, exactly 1 float4/thread.
// ---------------------------------------------------------------------------
__global__ void __launch_bounds__(NTHR, 2) k_fused(
    const int*   __restrict__ idx,
    const float* __restrict__ keys,
    const float* __restrict__ values,
    const float* __restrict__ q,
    float*       __restrict__ out)
{
    __shared__ int      js[CAP];
    __shared__ float    wls[CAP];
    __shared__ int      wsum[32];
    __shared__ float4   red4[32][33];        // padded transpose buffer
    __shared__ unsigned entry_phase;

    const int p    = blockIdx.x >> 1;
    const int h    = blockIdx.x & 1;
    const int tid  = threadIdx.x;
    const int lane = tid & 31;
    const int wid  = tid >> 5;

    if (tid == 0) entry_phase = g_bar_phase;   // snapshot before any release

    // ---- Phase 1a: strided-coalesced idx load (2 int4/thread), count
    const int4* idx4 = (const int4*)idx + h * (HALFN / 4);
    int4 my[PER];
    int cnt = 0;
    #pragma unroll
    for (int i = 0; i < PER; i++) {
        my[i] = idx4[i * NTHR + tid];
        cnt += (my[i].x == p) + (my[i].y == p) + (my[i].z == p) + (my[i].w == p);
    }

    // ---- Phase 1b: two-level exclusive scan (warp shfl + 32-entry top)
    int inc = cnt;
    #pragma unroll
    for (int o = 1; o < 32; o <<= 1) {
        int v = __shfl_up_sync(0xFFFFFFFFu, inc, o);
        if (lane >= o) inc += v;
    }
    if (lane == 31) wsum[wid] = inc;
    __syncthreads();
    if (wid == 0) {
        int v = wsum[lane];
        #pragma unroll
        for (int o = 1; o < 32; o <<= 1) {
            int u = __shfl_up_sync(0xFFFFFFFFu, v, o);
            if (lane >= o) v += u;
        }
        wsum[lane] = v;                        // inclusive prefix of warp totals
    }
    __syncthreads();
    int n   = wsum[31];
    int pos = (wid ? wsum[wid - 1] : 0) + (inc - cnt);

    // ---- Phase 1c: emit matched pair indices (fixed deterministic order)
    #pragma unroll
    for (int i = 0; i < PER; i++) {
        const int j = h * HALFN + (i * NTHR + tid) * 4;
        if (my[i].x == p && pos < CAP) js[pos++] = j + 0;
        if (my[i].y == p && pos < CAP) js[pos++] = j + 1;
        if (my[i].z == p && pos < CAP) js[pos++] = j + 2;
        if (my[i].w == p && pos < CAP) js[pos++] = j + 3;
    }
    if (n > CAP) n = CAP;
    __syncthreads();

    // ---- Phase 1.5: weights, 8 threads per 128B key row, octet shfl.
    // Capacity 128 rows per sweep; n~=64 -> single sweep, 512 active threads.
    {
        const int lane8 = tid & 7;
        const int row8  = tid >> 3;
        for (int base = 0; base < n; base += NTHR / 8) {
            const int m = base + row8;
            float s = 0.f;
            if (m < n) {
                float4 v = ((const float4*)keys)[(size_t)js[m] * (Cc / 4) + lane8];
                s = (v.x + v.y) + (v.z + v.w);
            }
            s += __shfl_xor_sync(0xFFFFFFFFu, s, 1);
            s += __shfl_xor_sync(0xFFFFFFFFu, s, 2);
            s += __shfl_xor_sync(0xFFFFFFFFu, s, 4);
            if (m < n && lane8 == 0) wls[m] = s * (1.0f / Cc);
        }
    }
    __syncthreads();

    // ---- Phase 2: float4 gather, thread=(slice,d4); ~2 matches per thread.
    {
        const int slice = tid >> 5;
        const int d4    = tid & 31;
        const float4* V4 = (const float4*)values;
        float4 acc = make_float4(0.f, 0.f, 0.f, 0.f);
        for (int m = slice; m < n; m += 32) {
            const float w = wls[m];
            float4 v = V4[(js[m] >> 1) * 32 + d4];
            acc.x += w * v.x; acc.y += w * v.y;
            acc.z += w * v.z; acc.w += w * v.w;
        }
        red4[slice][d4] = acc;
        __syncthreads();
        // warp-transpose reduce: warp `wid` owns column d4=wid, lanes=slices
        float4 v = red4[lane][wid];
        #pragma unroll
        for (int o = 16; o >= 1; o >>= 1) {
            v.x += __shfl_down_sync(0xFFFFFFFFu, v.x, o);
            v.y += __shfl_down_sync(0xFFFFFFFFu, v.y, o);
            v.z += __shfl_down_sync(0xFFFFFFFFu, v.z, o);
            v.w += __shfl_down_sync(0xFFFFFFFFu, v.w, o);
        }
        if (lane == 0)
            ((float4*)g_P)[(h * NP + p) * 32 + wid] = v;
    }

    // ---- Prefetch phase-3 inputs (independent of g_P) before the barrier
    const int    base = blockIdx.x * NTHR + tid;   // 0 .. 262143, 1 f4/thread
    const int2   ii   = ((const int2*)idx)[base >> 5];
    const float4 qv   = ((const float4*)q)[base];

    // ---- Grid barrier (256 arrivals; all CTAs co-resident at 2/SM)
    __syncthreads();
    if (tid == 0) {
        __threadfence();                           // publish g_P
        const unsigned tgt = entry_phase + 1;
        if (atomicAdd(&g_bar_count, 1u) == NBLK - 1) {
            g_bar_count = 0;
            __threadfence();
            g_bar_phase = tgt;                     // release
        } else {
            while (g_bar_phase < tgt) __nanosleep(32);
        }
    }
    __syncthreads();

    // ---- Phase 3: one float4 per thread; P rows are L2-resident
    {
        const int d4 = base & 31;
        const float4* P0 = (const float4*)g_P;     // half-0 rows
        const float4* P1 = P0 + NP * (Dd / 4);     // half-1 rows
        float4 a0 = P0[ii.x * 32 + d4];
        float4 b0 = P1[ii.x * 32 + d4];
        float4 a1 = P0[ii.y * 32 + d4];
        float4 b1 = P1[ii.y * 32 + d4];
        float4 o;
        o.x = ((a0.x + b0.x) + (a1.x + b1.x)) * qv.x;
        o.y = ((a0.y + b0.y) + (a1.y + b1.y)) * qv.y;
        o.z = ((a0.z + b0.z) + (a1.z + b1.z)) * qv.z;
        o.w = ((a0.w + b0.w) + (a1.w + b1.w)) * qv.w;
        ((float4*)out)[base] = o;
    }
}

extern "C" void kernel_launch(void* const* d_in, const int* in_sizes, int n_in,
                              void* d_out, int out_size)
{
    const int*   idx     = (const int*)  d_in[0];  // [B,S,K] int32
    const float* keys    = (const float*)d_in[1];  // [B,S,K,C] f32
    const float* values  = (const float*)d_in[2];  // [B,S,D]   f32
    const float* queries = (const float*)d_in[3];  // [B,S,D]   f32
    float*       out     = (float*)d_out;          // [B,S,D]   f32

    (void)in_sizes; (void)n_in; (void)out_size;

    k_fused<<<NBLK, NTHR>>>(idx, keys, values, queries, out);
}